// round 13
// baseline (speedup 1.0000x reference)
#include <cuda_runtime.h>
#include <math.h>

#define NB 8
#define NSEQ 1024
#define NC 768
#define NH 12
#define NDH 64
#define SCALE 0.125f
#define FIXMAX 12.0f

// ---------------- device scratch (no allocation allowed) --------------------
__device__ float g_Wq_hi[768 * 768];
__device__ float g_Wkv_hi[768 * 1536];
__device__ float g_Wp_hi[768 * 768],  g_Wp_lo[768 * 768];
__device__ float g_qin_hi[NB * NSEQ * NC], g_qin_lo[NB * NSEQ * NC];
__device__ float g_kin_hi[NB * NSEQ * NC], g_kin_lo[NB * NSEQ * NC];
__device__ float g_qh_hi[NB * NH * NSEQ * NDH], g_qh_lo[NB * NH * NSEQ * NDH];
__device__ float g_kh_hi[NB * NH * NSEQ * NDH];
__device__ float g_vh_hi[NB * NH * NSEQ * NDH];
__device__ float g_fpart[96 * 4 * 4096];
__device__ float g_fattn[NB * NH * NDH * NDH];
__device__ float g_tmp[NB * NSEQ * NC];

__device__ __forceinline__ unsigned f2tf(float x) {
    unsigned r;
    asm("cvt.rna.tf32.f32 %0, %1;" : "=r"(r) : "f"(x));
    return r;
}
__device__ __forceinline__ void split(float x, unsigned& hi, unsigned& lo) {
    unsigned h = f2tf(x);
    hi = h;
    lo = f2tf(x - __uint_as_float(h));
}
__device__ __forceinline__ void splitf(float x, float& hi, float& lo) {
    unsigned h, l;
    split(x, h, l);
    hi = __uint_as_float(h);
    lo = __uint_as_float(l);
}
__device__ __forceinline__ unsigned u32(float x) { return __float_as_uint(x); }

__device__ __forceinline__ void mma8(float d[4], const unsigned a[4],
                                     unsigned b0, unsigned b1) {
    asm volatile(
        "mma.sync.aligned.m16n8k8.row.col.f32.tf32.tf32.f32 "
        "{%0,%1,%2,%3}, {%4,%5,%6,%7}, {%8,%9}, {%0,%1,%2,%3};"
        : "+f"(d[0]), "+f"(d[1]), "+f"(d[2]), "+f"(d[3])
        : "r"(a[0]), "r"(a[1]), "r"(a[2]), "r"(a[3]), "r"(b0), "r"(b1));
}
__device__ __forceinline__ void mma3(float d[4],
                                     const unsigned ah[4], const unsigned al[4],
                                     unsigned bh0, unsigned bh1,
                                     unsigned bl0, unsigned bl1) {
    mma8(d, al, bh0, bh1);
    mma8(d, ah, bl0, bl1);
    mma8(d, ah, bh0, bh1);
}

__device__ __forceinline__ unsigned smem_u32(const void* p) {
    return (unsigned)__cvta_generic_to_shared(p);
}
__device__ __forceinline__ void cpa16(unsigned dst, const void* src) {
    asm volatile("cp.async.ca.shared.global [%0], [%1], 16;" :: "r"(dst), "l"(src));
}
#define CP_COMMIT asm volatile("cp.async.commit_group;" ::: "memory")
#define CP_WAIT0  asm volatile("cp.async.wait_group 0;" ::: "memory")

// ---------------------------------------------------------------------------
// Kernel 0: pre-split weights AND activation inputs.
// float4 counts: Wq 147456 | Wkv 294912 | Wp 147456 | qin 1572864 | kin 1572864
// ---------------------------------------------------------------------------
__global__ __launch_bounds__(256) void prep_split(const float* __restrict__ Wq,
                                                  const float* __restrict__ Wkv,
                                                  const float* __restrict__ Wp,
                                                  const float* __restrict__ qin,
                                                  const float* __restrict__ kin) {
    const int idx = blockIdx.x * 256 + threadIdx.x;
    const int NQ = 147456, NKV = 294912, NP = 147456, NACT = 1572864;
    if (idx < NQ) {
        float4 v = ((const float4*)Wq)[idx];
        float4 h;
        h.x = __uint_as_float(f2tf(v.x));
        h.y = __uint_as_float(f2tf(v.y));
        h.z = __uint_as_float(f2tf(v.z));
        h.w = __uint_as_float(f2tf(v.w));
        ((float4*)g_Wq_hi)[idx] = h;
    } else if (idx < NQ + NKV) {
        const int off = idx - NQ;
        float4 v = ((const float4*)Wkv)[off];
        float4 h;
        h.x = __uint_as_float(f2tf(v.x));
        h.y = __uint_as_float(f2tf(v.y));
        h.z = __uint_as_float(f2tf(v.z));
        h.w = __uint_as_float(f2tf(v.w));
        ((float4*)g_Wkv_hi)[off] = h;
    } else if (idx < NQ + NKV + NP) {
        const int off = idx - NQ - NKV;
        float4 v = ((const float4*)Wp)[off];
        float4 h, l;
        splitf(v.x, h.x, l.x);
        splitf(v.y, h.y, l.y);
        splitf(v.z, h.z, l.z);
        splitf(v.w, h.w, l.w);
        ((float4*)g_Wp_hi)[off] = h;
        ((float4*)g_Wp_lo)[off] = l;
    } else if (idx < NQ + NKV + NP + NACT) {
        const int off = idx - NQ - NKV - NP;
        float4 v = ((const float4*)qin)[off];
        float4 h, l;
        splitf(v.x, h.x, l.x);
        splitf(v.y, h.y, l.y);
        splitf(v.z, h.z, l.z);
        splitf(v.w, h.w, l.w);
        ((float4*)g_qin_hi)[off] = h;
        ((float4*)g_qin_lo)[off] = l;
    } else if (idx < NQ + NKV + NP + 2 * NACT) {
        const int off = idx - NQ - NKV - NP - NACT;
        float4 v = ((const float4*)kin)[off];
        float4 h, l;
        splitf(v.x, h.x, l.x);
        splitf(v.y, h.y, l.y);
        splitf(v.z, h.z, l.z);
        splitf(v.w, h.w, l.w);
        ((float4*)g_kin_hi)[off] = h;
        ((float4*)g_kin_lo)[off] = l;
    }
}

// ---------------------------------------------------------------------------
// Kernel 1: fused QKV projection. 2-mma: A pre-split (hi+lo staged), B hi.
// dsm floats: (Ah 4608|Al 4608) x2 bufs at 0 (18432); Bh[2][4352] at 18432.
// total 27136 floats = 108544 B.
// ---------------------------------------------------------------------------
__global__ __launch_bounds__(256, 2) void qkv_gemm() {
    extern __shared__ float dsm[];

    const int n0 = blockIdx.x * 128;
    const int m0 = blockIdx.y * 128;
    const bool isQ = (n0 < 768);
    const float* AH = isQ ? g_qin_hi : g_kin_hi;
    const float* AL = isQ ? g_qin_lo : g_kin_lo;
    const float* BmH = isQ ? g_Wq_hi : g_Wkv_hi;
    const int ldb = isQ ? 768 : 1536;
    const int cb  = isQ ? n0 : n0 - 768;

    const int t = threadIdx.x, lane = t & 31, w = t >> 5;
    const int g = lane >> 2, tg = lane & 3;
    const int wm = w & 3, wn = w >> 2;

    auto stageA = [&](float* Ah, float* Al, int k0) {
#pragma unroll
        for (int u = 0; u < 4; u++) {
            const int idx = t + u * 256;
            const int row = idx >> 3, colf = (idx & 7) * 4;
            const size_t go = (size_t)(m0 + row) * 768 + k0 + colf;
            cpa16(smem_u32(&Ah[row * 36 + colf]), AH + go);
            cpa16(smem_u32(&Al[row * 36 + colf]), AL + go);
        }
    };
    auto stageB = [&](float* Bh, int k0) {
#pragma unroll
        for (int u = 0; u < 4; u++) {
            const int idx = t + u * 256;
            const int row = idx >> 5, col = (idx & 31) * 4;
            cpa16(smem_u32(&Bh[row * 136 + col]),
                  BmH + (size_t)(k0 + row) * ldb + cb + col);
        }
    };

    float acc[2][8][4] = {};

    stageA(dsm, dsm + 4608, 0);
    stageB(dsm + 18432, 0);
    CP_COMMIT;
    CP_WAIT0;
    __syncthreads();

    for (int k0 = 0; k0 < 768; k0 += 32) {
        const int cur = (k0 >> 5) & 1;
        float* Ah = dsm + cur * 9216;
        float* Al = Ah + 4608;
        float* Bh = dsm + 18432 + cur * 4352;
        const bool more = (k0 + 32 < 768);
        if (more) {
            float* nAh = dsm + (cur ^ 1) * 9216;
            stageA(nAh, nAh + 4608, k0 + 32);
            stageB(dsm + 18432 + (cur ^ 1) * 4352, k0 + 32);
            CP_COMMIT;
        }
#pragma unroll
        for (int kk = 0; kk < 4; kk++) {
            const int k = kk * 8;
            unsigned ah[2][4], al[2][4];
#pragma unroll
            for (int i = 0; i < 2; i++) {
                const int rb = wm * 32 + i * 16 + g;
                ah[i][0] = u32(Ah[rb * 36 + k + tg]);
                ah[i][1] = u32(Ah[(rb + 8) * 36 + k + tg]);
                ah[i][2] = u32(Ah[rb * 36 + k + tg + 4]);
                ah[i][3] = u32(Ah[(rb + 8) * 36 + k + tg + 4]);
                al[i][0] = u32(Al[rb * 36 + k + tg]);
                al[i][1] = u32(Al[(rb + 8) * 36 + k + tg]);
                al[i][2] = u32(Al[rb * 36 + k + tg + 4]);
                al[i][3] = u32(Al[(rb + 8) * 36 + k + tg + 4]);
            }
#pragma unroll
            for (int j = 0; j < 8; j++) {
                const int c = wn * 64 + j * 8 + g;
                const unsigned bh0 = u32(Bh[(k + tg) * 136 + c]);
                const unsigned bh1 = u32(Bh[(k + tg + 4) * 136 + c]);
                mma8(acc[0][j], al[0], bh0, bh1);
                mma8(acc[0][j], ah[0], bh0, bh1);
                mma8(acc[1][j], al[1], bh0, bh1);
                mma8(acc[1][j], ah[1], bh0, bh1);
            }
        }
        if (more) {
            CP_WAIT0;
            __syncthreads();
        }
    }

    // epilogue: scatter head-major. q: hi+lo. k/v: hi only.
#pragma unroll
    for (int i = 0; i < 2; i++) {
        const int mA = m0 + wm * 32 + i * 16 + g;
#pragma unroll
        for (int half = 0; half < 2; half++) {
            const int m = mA + half * 8;
            const int bb = m >> 10, n = m & 1023;
#pragma unroll
            for (int j = 0; j < 8; j++) {
                const int cg = n0 + wn * 64 + j * 8 + tg * 2;
                const float x0 = acc[i][j][half * 2];
                const float x1 = acc[i][j][half * 2 + 1];
                if (cg < 768) {
                    float2 vh, vl;
                    splitf(x0, vh.x, vl.x);
                    splitf(x1, vh.y, vl.y);
                    const int h = cg >> 6, d = cg & 63;
                    const size_t o = (((size_t)bb * NH + h) * NSEQ + n) * NDH + d;
                    *(float2*)&g_qh_hi[o] = vh;
                    *(float2*)&g_qh_lo[o] = vl;
                } else {
                    const int cc = cg - 768;
                    const bool isV = (cc >= 768);
                    const int c2 = isV ? cc - 768 : cc;
                    const int h = c2 >> 6, d = c2 & 63;
                    const size_t o = (((size_t)bb * NH + h) * NSEQ + n) * NDH + d;
                    float2 vh = make_float2(__uint_as_float(f2tf(x0)),
                                            __uint_as_float(f2tf(x1)));
                    *(float2*)&(isV ? g_vh_hi : g_kh_hi)[o] = vh;
                }
            }
        }
    }
}

// ---------------------------------------------------------------------------
// Kernel 2a: feature attention PARTIAL. grid (96, 4): block sums 256 n each.
// 2-mma (Q exact x K-hi). Raw partial S -> g_fpart.
// dsm: 2 bufs x (Qh 2304 | Ql 2304 | Kh 2304), stride 72. 13824 f = 55296 B.
// ---------------------------------------------------------------------------
__global__ __launch_bounds__(128) void fattn_partial() {
    extern __shared__ float dsm[];

    const int bh = blockIdx.x;
    const int nbase = blockIdx.y * 256;
    const size_t base = (size_t)bh * NSEQ * NDH;

    const int t = threadIdx.x, lane = t & 31, w = t >> 5;
    const int g = lane >> 2, tg = lane & 3;
    const int mb = w * 16 + g;

    auto stage = [&](int buf, int n0) {
        float* p = dsm + buf * 6912;
#pragma unroll
        for (int u = 0; u < 4; u++) {
            const int idx = t + u * 128;
            const int row = idx >> 4, colf = (idx & 15) * 4;
            const size_t go = base + (size_t)(nbase + n0 + row) * 64 + colf;
            cpa16(smem_u32(&p[row * 72 + colf]),        g_qh_hi + go);
            cpa16(smem_u32(&p[2304 + row * 72 + colf]), g_qh_lo + go);
            cpa16(smem_u32(&p[4608 + row * 72 + colf]), g_kh_hi + go);
        }
    };

    float acc[8][4] = {};
    stage(0, 0);
    CP_COMMIT;
    CP_WAIT0;
    __syncthreads();

    for (int n0 = 0; n0 < 256; n0 += 32) {
        const int cur = (n0 >> 5) & 1;
        float* Qh = dsm + cur * 6912;
        float* Ql = Qh + 2304;
        float* Kh = Qh + 4608;
        const bool more = (n0 + 32 < 256);
        if (more) {
            stage(cur ^ 1, n0 + 32);
            CP_COMMIT;
        }
#pragma unroll
        for (int kk = 0; kk < 4; kk++) {
            const int k = kk * 8;
            unsigned ah[4], al[4];
            ah[0] = u32(Qh[(k + tg) * 72 + mb]);
            ah[1] = u32(Qh[(k + tg) * 72 + mb + 8]);
            ah[2] = u32(Qh[(k + tg + 4) * 72 + mb]);
            ah[3] = u32(Qh[(k + tg + 4) * 72 + mb + 8]);
            al[0] = u32(Ql[(k + tg) * 72 + mb]);
            al[1] = u32(Ql[(k + tg) * 72 + mb + 8]);
            al[2] = u32(Ql[(k + tg + 4) * 72 + mb]);
            al[3] = u32(Ql[(k + tg + 4) * 72 + mb + 8]);
#pragma unroll
            for (int j = 0; j < 8; j++) {
                const int c = j * 8 + g;
                const unsigned bh0 = u32(Kh[(k + tg) * 72 + c]);
                const unsigned bh1 = u32(Kh[(k + tg + 4) * 72 + c]);
                mma8(acc[j], al, bh0, bh1);
                mma8(acc[j], ah, bh0, bh1);
            }
        }
        if (more) {
            CP_WAIT0;
            __syncthreads();
        }
    }

    float* outp = g_fpart + ((size_t)bh * 4 + blockIdx.y) * 4096;
#pragma unroll
    for (int j = 0; j < 8; j++) {
        const int r0 = w * 16 + g, c = j * 8 + tg * 2;
        *(float2*)&outp[r0 * 64 + c]       = make_float2(acc[j][0], acc[j][1]);
        *(float2*)&outp[(r0 + 8) * 64 + c] = make_float2(acc[j][2], acc[j][3]);
    }
}

// ---------------------------------------------------------------------------
// Kernel 2b: combine partials + softmax + tf32 round. 96 blocks x 64 threads.
// ---------------------------------------------------------------------------
__global__ __launch_bounds__(64) void fattn_soft() {
    const int bh = blockIdx.x, t = threadIdx.x;
    const float* p0 = g_fpart + ((size_t)bh * 4 + 0) * 4096 + t * 64;
    const float* p1 = g_fpart + ((size_t)bh * 4 + 1) * 4096 + t * 64;
    const float* p2 = g_fpart + ((size_t)bh * 4 + 2) * 4096 + t * 64;
    const float* p3 = g_fpart + ((size_t)bh * 4 + 3) * 4096 + t * 64;
    float row[64];
    float mx = -INFINITY;
#pragma unroll 8
    for (int e = 0; e < 64; e++) {
        const float s = ((p0[e] + p1[e]) + (p2[e] + p3[e])) * SCALE;
        row[e] = s;
        mx = fmaxf(mx, s);
    }
    float sum = 0.f;
#pragma unroll 8
    for (int e = 0; e < 64; e++) {
        const float v = __expf(row[e] - mx);
        row[e] = v;
        sum += v;
    }
    const float inv = 1.0f / sum;
    float* outp = g_fattn + (size_t)bh * 4096 + t * 64;
#pragma unroll 8
    for (int e = 0; e < 64; e++)
        outp[e] = __uint_as_float(f2tf(row[e] * inv));
}

// ---------------------------------------------------------------------------
// Kernel 3: flash attention + feature apply. FIXED-MAX softmax, 3 CTAs/SM.
// ---------------------------------------------------------------------------
__global__ __launch_bounds__(128, 3) void attn_kernel() {
    extern __shared__ float dsm[];

    const int bh = blockIdx.y;
    const int n0q = blockIdx.x * 64;
    const size_t base = (size_t)bh * NSEQ * NDH;

    const int t = threadIdx.x, lane = t & 31, w = t >> 5;
    const int g = lane >> 2, tg = lane & 3;

    auto stageKV = [&](int buf, int c0) {
        float* Kh = dsm + 8704 + buf * 2176;
        float* Vh = dsm + 13056 + buf * 2304;
#pragma unroll
        for (int u = 0; u < 4; u++) {
            const int idx = t + u * 128;
            const int row = idx >> 4, colf = (idx & 15) * 4;
            const size_t go = base + (size_t)(c0 + row) * 64 + colf;
            cpa16(smem_u32(&Kh[row * 68 + colf]), g_kh_hi + go);
            cpa16(smem_u32(&Vh[row * 72 + colf]), g_vh_hi + go);
        }
    };

#pragma unroll
    for (int u = 0; u < 8; u++) {
        const int idx = t + u * 128;
        const int row = idx >> 4, colf = (idx & 15) * 4;
        const size_t go = base + (size_t)(n0q + row) * 64 + colf;
        cpa16(smem_u32(&dsm[row * 68 + colf]),        g_qh_hi + go);
        cpa16(smem_u32(&dsm[4352 + row * 68 + colf]), g_qh_lo + go);
    }
    stageKV(0, 0);
    CP_COMMIT;
    CP_WAIT0;
    __syncthreads();

    unsigned qfh[8][4], qfl[8][4];
    {
        const int rb = w * 16 + g;
#pragma unroll
        for (int kk = 0; kk < 8; kk++) {
            const int k = kk * 8;
            qfh[kk][0] = u32(dsm[rb * 68 + k + tg]);
            qfh[kk][1] = u32(dsm[(rb + 8) * 68 + k + tg]);
            qfh[kk][2] = u32(dsm[rb * 68 + k + tg + 4]);
            qfh[kk][3] = u32(dsm[(rb + 8) * 68 + k + tg + 4]);
            qfl[kk][0] = u32(dsm[4352 + rb * 68 + k + tg]);
            qfl[kk][1] = u32(dsm[4352 + (rb + 8) * 68 + k + tg]);
            qfl[kk][2] = u32(dsm[4352 + rb * 68 + k + tg + 4]);
            qfl[kk][3] = u32(dsm[4352 + (rb + 8) * 68 + k + tg + 4]);
        }
    }
    __syncthreads();   // Q region now reusable (P)

    float O[8][4] = {};
    float l0 = 0.f, l1 = 0.f;
    float* Pw = dsm + w * 576;

    for (int c0 = 0; c0 < NSEQ; c0 += 32) {
        const int cur = (c0 >> 5) & 1;
        float* Kh = dsm + 8704 + cur * 2176;
        float* Vh = dsm + 13056 + cur * 2304;
        const bool more = (c0 + 32 < NSEQ);
        if (more) {
            stageKV(cur ^ 1, c0 + 32);
            CP_COMMIT;
        }

        float sacc[4][4] = {};
#pragma unroll
        for (int kk = 0; kk < 8; kk++) {
            const int k = kk * 8;
#pragma unroll
            for (int j = 0; j < 4; j++) {
                const int c = j * 8 + g;
                const unsigned bh0 = u32(Kh[c * 68 + k + tg]);
                const unsigned bh1 = u32(Kh[c * 68 + k + tg + 4]);
                mma8(sacc[j], qfl[kk], bh0, bh1);
                mma8(sacc[j], qfh[kk], bh0, bh1);
            }
        }

#pragma unroll
        for (int j = 0; j < 4; j++) {
            const float p00 = __expf(fmaf(sacc[j][0], SCALE, -FIXMAX));
            const float p01 = __expf(fmaf(sacc[j][1], SCALE, -FIXMAX));
            const float p10 = __expf(fmaf(sacc[j][2], SCALE, -FIXMAX));
            const float p11 = __expf(fmaf(sacc[j][3], SCALE, -FIXMAX));
            l0 += p00 + p01;
            l1 += p10 + p11;
            const int c = j * 8 + tg * 2;
            Pw[g * 36 + c]           = __uint_as_float(f2tf(p00));
            Pw[g * 36 + c + 1]       = __uint_as_float(f2tf(p01));
            Pw[(g + 8) * 36 + c]     = __uint_as_float(f2tf(p10));
            Pw[(g + 8) * 36 + c + 1] = __uint_as_float(f2tf(p11));
        }
        __syncwarp();

#pragma unroll
        for (int kk = 0; kk < 4; kk++) {
            const int k = kk * 8;
            unsigned a[4];
            a[0] = u32(Pw[g * 36 + k + tg]);
            a[1] = u32(Pw[(g + 8) * 36 + k + tg]);
            a[2] = u32(Pw[g * 36 + k + tg + 4]);
            a[3] = u32(Pw[(g + 8) * 36 + k + tg + 4]);
#pragma unroll
            for (int nt = 0; nt < 8; nt++) {
                const unsigned b0 = u32(Vh[(k + tg) * 72 + nt * 8 + g]);
                const unsigned b1 = u32(Vh[(k + tg + 4) * 72 + nt * 8 + g]);
                mma8(O[nt], a, b0, b1);
            }
        }

        if (more) {
            CP_WAIT0;
        }
        __syncthreads();
    }

    l0 += __shfl_xor_sync(0xffffffffu, l0, 1);
    l0 += __shfl_xor_sync(0xffffffffu, l0, 2);
    l1 += __shfl_xor_sync(0xffffffffu, l1, 1);
    l1 += __shfl_xor_sync(0xffffffffu, l1, 2);
    const float i0 = 1.0f / l0, i1 = 1.0f / l1;
#pragma unroll
    for (int nt = 0; nt < 8; nt++) {
        O[nt][0] *= i0; O[nt][1] *= i0;
        O[nt][2] *= i1; O[nt][3] *= i1;
    }

    // feature path
    float* Fa  = dsm;
    float* Vqh = dsm + 4352;
    const float* Fg = g_fattn + (size_t)bh * 4096;
    {
#pragma unroll
        for (int u = 0; u < 8; u++) {
            const int idx = t + u * 128;
            const int row = idx >> 4, colf = (idx & 15) * 4;
            const size_t go = base + (size_t)(n0q + row) * 64 + colf;
            cpa16(smem_u32(&Fa[row * 68 + colf]), Fg + (size_t)row * 64 + colf);
            cpa16(smem_u32(&Vqh[row * 68 + colf]), g_vh_hi + go);
        }
    }
    CP_COMMIT;
    CP_WAIT0;
    __syncthreads();
    {
        const int rb = w * 16 + g;
#pragma unroll
        for (int kk = 0; kk < 8; kk++) {
            const int k = kk * 8;
            unsigned a[4];
            a[0] = u32(Vqh[rb * 68 + k + tg]);
            a[1] = u32(Vqh[(rb + 8) * 68 + k + tg]);
            a[2] = u32(Vqh[rb * 68 + k + tg + 4]);
            a[3] = u32(Vqh[(rb + 8) * 68 + k + tg + 4]);
#pragma unroll
            for (int nt = 0; nt < 8; nt++) {
                const unsigned b0 = u32(Fa[(nt * 8 + g) * 68 + k + tg]);
                const unsigned b1 = u32(Fa[(nt * 8 + g) * 68 + k + tg + 4]);
                mma8(O[nt], a, b0, b1);
            }
        }
    }

    const int bb = bh / NH, h = bh - bb * NH;
    const int r0 = n0q + w * 16 + g;
#pragma unroll
    for (int nt = 0; nt < 8; nt++) {
        const int col = h * 64 + nt * 8 + tg * 2;
        *(float2*)&g_tmp[((size_t)bb * NSEQ + r0) * NC + col] =
            make_float2(O[nt][0], O[nt][1]);
        *(float2*)&g_tmp[((size_t)bb * NSEQ + r0 + 8) * NC + col] =
            make_float2(O[nt][2], O[nt][3]);
    }
}

// ---------------------------------------------------------------------------
// Kernel 4: output projection, 3xtf32 (guards the error budget).
// ---------------------------------------------------------------------------
__global__ __launch_bounds__(256, 2) void proj_gemm(const float* __restrict__ bias,
                                                    float* __restrict__ out) {
    extern __shared__ float dsm[];

    const int n0 = blockIdx.x * 128;
    const int m0 = blockIdx.y * 128;
    const int t = threadIdx.x, lane = t & 31, w = t >> 5;
    const int g = lane >> 2, tg = lane & 3;
    const int wm = w & 3, wn = w >> 2;

    auto stageA = [&](float* As, int k0) {
#pragma unroll
        for (int u = 0; u < 4; u++) {
            const int idx = t + u * 256;
            const int row = idx >> 3, colf = (idx & 7) * 4;
            cpa16(smem_u32(&As[row * 36 + colf]),
                  g_tmp + (size_t)(m0 + row) * 768 + k0 + colf);
        }
    };
    auto stageB = [&](float* Bh, float* Bl, int k0) {
#pragma unroll
        for (int u = 0; u < 4; u++) {
            const int idx = t + u * 256;
            const int row = idx >> 5, col = (idx & 31) * 4;
            const size_t go = (size_t)(k0 + row) * 768 + n0 + col;
            cpa16(smem_u32(&Bh[row * 136 + col]), g_Wp_hi + go);
            cpa16(smem_u32(&Bl[row * 136 + col]), g_Wp_lo + go);
        }
    };

    float acc[2][8][4] = {};

    stageA(dsm, 0);
    stageB(dsm + 9216, dsm + 9216 + 4352, 0);
    CP_COMMIT;
    CP_WAIT0;
    __syncthreads();

    for (int k0 = 0; k0 < 768; k0 += 32) {
        const int cur = (k0 >> 5) & 1;
        float* As = dsm + cur * 4608;
        float* Bh = dsm + 9216 + cur * 8704;
        float* Bl = Bh + 4352;
        const bool more = (k0 + 32 < 768);
        if (more) {
            stageA(dsm + (cur ^ 1) * 4608, k0 + 32);
            stageB(dsm + 9216 + (cur ^ 1) * 8704,
                   dsm + 9216 + (cur ^ 1) * 8704 + 4352, k0 + 32);
            CP_COMMIT;
        }
#pragma unroll
        for (int kk = 0; kk < 4; kk++) {
            const int k = kk * 8;
            unsigned ah[2][4], al[2][4];
#pragma unroll
            for (int i = 0; i < 2; i++) {
                const int rb = wm * 32 + i * 16 + g;
                split(As[rb * 36 + k + tg],           ah[i][0], al[i][0]);
                split(As[(rb + 8) * 36 + k + tg],     ah[i][1], al[i][1]);
                split(As[rb * 36 + k + tg + 4],       ah[i][2], al[i][2]);
                split(As[(rb + 8) * 36 + k + tg + 4], ah[i][3], al[i][3]);
            }
#pragma unroll
            for (int j = 0; j < 8; j++) {
                const int c = wn * 64 + j * 8 + g;
                const unsigned bh0 = u32(Bh[(k + tg) * 136 + c]);
                const unsigned bh1 = u32(Bh[(k + tg + 4) * 136 + c]);
                const unsigned bl0 = u32(Bl[(k + tg) * 136 + c]);
                const unsigned bl1 = u32(Bl[(k + tg + 4) * 136 + c]);
                mma3(acc[0][j], ah[0], al[0], bh0, bh1, bl0, bl1);
                mma3(acc[1][j], ah[1], al[1], bh0, bh1, bl0, bl1);
            }
        }
        if (more) {
            CP_WAIT0;
            __syncthreads();
        }
    }

#pragma unroll
    for (int i = 0; i < 2; i++) {
        const int mA = m0 + wm * 32 + i * 16 + g;
#pragma unroll
        for (int half = 0; half < 2; half++) {
            const size_t m = mA + half * 8;
#pragma unroll
            for (int j = 0; j < 8; j++) {
                const int c = n0 + wn * 64 + j * 8 + tg * 2;
                float2 v = make_float2(acc[i][j][half * 2] + bias[c],
                                       acc[i][j][half * 2 + 1] + bias[c + 1]);
                *(float2*)&out[m * 768 + c] = v;
            }
        }
    }
}

// ---------------------------------------------------------------------------
extern "C" void kernel_launch(void* const* d_in, const int* in_sizes, int n_in,
                              void* d_out, int out_size) {
    const float* q     = (const float*)d_in[0];
    const float* k     = (const float*)d_in[1];
    const float* Wq    = (const float*)d_in[2];
    const float* Wkv   = (const float*)d_in[3];
    const float* Wproj = (const float*)d_in[4];
    const float* bproj = (const float*)d_in[5];
    float* out = (float*)d_out;

    const int smemQ = 27136 * 4;   // 108544 B
    const int smemP = 26624 * 4;   // 106496 B
    const int smemA = 17664 * 4;   // 70656 B
    const int smemF = 13824 * 4;   // 55296 B
    cudaFuncSetAttribute(qkv_gemm, cudaFuncAttributeMaxDynamicSharedMemorySize, smemQ);
    cudaFuncSetAttribute(proj_gemm, cudaFuncAttributeMaxDynamicSharedMemorySize, smemP);
    cudaFuncSetAttribute(attn_kernel, cudaFuncAttributeMaxDynamicSharedMemorySize, smemA);
    cudaFuncSetAttribute(fattn_partial, cudaFuncAttributeMaxDynamicSharedMemorySize, smemF);

    // weights 589824 f4 + activations 2*1572864 f4 = 3735552 f4; /256 = 14592 blocks
    prep_split<<<14592, 256>>>(Wq, Wkv, Wproj, q, k);
    qkv_gemm<<<dim3(18, 64), 256, smemQ>>>();
    fattn_partial<<<dim3(96, 4), 128, smemF>>>();
    fattn_soft<<<96, 64>>>();
    attn_kernel<<<dim3(16, 96), 128, smemA>>>();
    proj_gemm<<<dim3(6, 64), 256, smemP>>>(bproj, out);
}

// round 14
// speedup vs baseline: 1.0863x; 1.0863x over previous
#include <cuda_runtime.h>
#include <math.h>

#define NB 8
#define NSEQ 1024
#define NC 768
#define NH 12
#define NDH 64
#define SCALE 0.125f
#define FIXMAX 12.0f

// ---------------- device scratch (no allocation allowed) --------------------
__device__ float g_Wq_hi[768 * 768];
__device__ float g_Wkv_hi[768 * 1536];
__device__ float g_Wp_hi[768 * 768],  g_Wp_lo[768 * 768];
__device__ float g_qh_hi[NB * NH * NSEQ * NDH], g_qh_lo[NB * NH * NSEQ * NDH];
__device__ float g_kh_hi[NB * NH * NSEQ * NDH];
__device__ float g_vh_hi[NB * NH * NSEQ * NDH];
__device__ float g_fpart[96 * 4 * 4096];          // fattn split-K partials
__device__ float g_fattn[NB * NH * NDH * NDH];    // tf32-rounded
__device__ float g_tmp[NB * NSEQ * NC];

__device__ __forceinline__ unsigned f2tf(float x) {
    unsigned r;
    asm("cvt.rna.tf32.f32 %0, %1;" : "=r"(r) : "f"(x));
    return r;
}
__device__ __forceinline__ void split(float x, unsigned& hi, unsigned& lo) {
    unsigned h = f2tf(x);
    hi = h;
    lo = f2tf(x - __uint_as_float(h));
}
__device__ __forceinline__ void splitf(float x, float& hi, float& lo) {
    unsigned h, l;
    split(x, h, l);
    hi = __uint_as_float(h);
    lo = __uint_as_float(l);
}
__device__ __forceinline__ unsigned u32(float x) { return __float_as_uint(x); }

__device__ __forceinline__ void mma8(float d[4], const unsigned a[4],
                                     unsigned b0, unsigned b1) {
    asm volatile(
        "mma.sync.aligned.m16n8k8.row.col.f32.tf32.tf32.f32 "
        "{%0,%1,%2,%3}, {%4,%5,%6,%7}, {%8,%9}, {%0,%1,%2,%3};"
        : "+f"(d[0]), "+f"(d[1]), "+f"(d[2]), "+f"(d[3])
        : "r"(a[0]), "r"(a[1]), "r"(a[2]), "r"(a[3]), "r"(b0), "r"(b1));
}
__device__ __forceinline__ void mma3(float d[4],
                                     const unsigned ah[4], const unsigned al[4],
                                     unsigned bh0, unsigned bh1,
                                     unsigned bl0, unsigned bl1) {
    mma8(d, al, bh0, bh1);
    mma8(d, ah, bl0, bl1);
    mma8(d, ah, bh0, bh1);
}

__device__ __forceinline__ unsigned smem_u32(const void* p) {
    return (unsigned)__cvta_generic_to_shared(p);
}
__device__ __forceinline__ void cpa16(unsigned dst, const void* src) {
    asm volatile("cp.async.ca.shared.global [%0], [%1], 16;" :: "r"(dst), "l"(src));
}
#define CP_COMMIT asm volatile("cp.async.commit_group;" ::: "memory")
#define CP_WAIT0  asm volatile("cp.async.wait_group 0;" ::: "memory")

// ---------------------------------------------------------------------------
// Kernel 0: pre-split weights. Wq/Wkv hi only; Wp hi+lo. (R11 version)
// ---------------------------------------------------------------------------
__global__ __launch_bounds__(256) void prep_split(const float* __restrict__ Wq,
                                                  const float* __restrict__ Wkv,
                                                  const float* __restrict__ Wp) {
    const int idx = blockIdx.x * 256 + threadIdx.x;
    const int NQ = 147456, NKV = 294912;
    if (idx < NQ) {
        float4 v = ((const float4*)Wq)[idx];
        float4 h;
        h.x = __uint_as_float(f2tf(v.x));
        h.y = __uint_as_float(f2tf(v.y));
        h.z = __uint_as_float(f2tf(v.z));
        h.w = __uint_as_float(f2tf(v.w));
        ((float4*)g_Wq_hi)[idx] = h;
    } else if (idx < NQ + NKV) {
        const int off = idx - NQ;
        float4 v = ((const float4*)Wkv)[off];
        float4 h;
        h.x = __uint_as_float(f2tf(v.x));
        h.y = __uint_as_float(f2tf(v.y));
        h.z = __uint_as_float(f2tf(v.z));
        h.w = __uint_as_float(f2tf(v.w));
        ((float4*)g_Wkv_hi)[off] = h;
    } else {
        const int off = idx - NQ - NKV;
        float4 v = ((const float4*)Wp)[off];
        float4 h, l;
        splitf(v.x, h.x, l.x);
        splitf(v.y, h.y, l.y);
        splitf(v.z, h.z, l.z);
        splitf(v.w, h.w, l.w);
        ((float4*)g_Wp_hi)[off] = h;
        ((float4*)g_Wp_lo)[off] = l;
    }
}

// ---------------------------------------------------------------------------
// Kernel 1: fused QKV projection. 2-mma: A f32 (inline split), B hi. (R11)
// dsm floats: A[2][4608] at 0; Bh[2][4352] at 9216. total 17920 (71.7 KB).
// ---------------------------------------------------------------------------
__global__ __launch_bounds__(256, 2) void qkv_gemm(const float* __restrict__ q,
                                                   const float* __restrict__ kx) {
    extern __shared__ float dsm[];

    const int n0 = blockIdx.x * 128;
    const int m0 = blockIdx.y * 128;
    const bool isQ = (n0 < 768);
    const float* A = isQ ? q : kx;
    const float* BmH = isQ ? g_Wq_hi : g_Wkv_hi;
    const int ldb = isQ ? 768 : 1536;
    const int cb  = isQ ? n0 : n0 - 768;

    const int t = threadIdx.x, lane = t & 31, w = t >> 5;
    const int g = lane >> 2, tg = lane & 3;
    const int wm = w & 3, wn = w >> 2;

    auto stageA = [&](float* As, int k0) {
#pragma unroll
        for (int u = 0; u < 4; u++) {
            const int idx = t + u * 256;
            const int row = idx >> 3, colf = (idx & 7) * 4;
            cpa16(smem_u32(&As[row * 36 + colf]),
                  A + (size_t)(m0 + row) * 768 + k0 + colf);
        }
    };
    auto stageB = [&](float* Bh, int k0) {
#pragma unroll
        for (int u = 0; u < 4; u++) {
            const int idx = t + u * 256;
            const int row = idx >> 5, col = (idx & 31) * 4;
            cpa16(smem_u32(&Bh[row * 136 + col]),
                  BmH + (size_t)(k0 + row) * ldb + cb + col);
        }
    };

    float acc[2][8][4] = {};

    stageA(dsm, 0);
    stageB(dsm + 9216, 0);
    CP_COMMIT;
    CP_WAIT0;
    __syncthreads();

    for (int k0 = 0; k0 < 768; k0 += 32) {
        const int cur = (k0 >> 5) & 1;
        float* As = dsm + cur * 4608;
        float* Bh = dsm + 9216 + cur * 4352;
        const bool more = (k0 + 32 < 768);
        if (more) {
            stageA(dsm + (cur ^ 1) * 4608, k0 + 32);
            stageB(dsm + 9216 + (cur ^ 1) * 4352, k0 + 32);
            CP_COMMIT;
        }
#pragma unroll
        for (int kk = 0; kk < 4; kk++) {
            const int k = kk * 8;
            unsigned ah[2][4], al[2][4];
#pragma unroll
            for (int i = 0; i < 2; i++) {
                const int rb = wm * 32 + i * 16 + g;
                split(As[rb * 36 + k + tg],           ah[i][0], al[i][0]);
                split(As[(rb + 8) * 36 + k + tg],     ah[i][1], al[i][1]);
                split(As[rb * 36 + k + tg + 4],       ah[i][2], al[i][2]);
                split(As[(rb + 8) * 36 + k + tg + 4], ah[i][3], al[i][3]);
            }
#pragma unroll
            for (int j = 0; j < 8; j++) {
                const int c = wn * 64 + j * 8 + g;
                const unsigned bh0 = u32(Bh[(k + tg) * 136 + c]);
                const unsigned bh1 = u32(Bh[(k + tg + 4) * 136 + c]);
                mma8(acc[0][j], al[0], bh0, bh1);
                mma8(acc[0][j], ah[0], bh0, bh1);
                mma8(acc[1][j], al[1], bh0, bh1);
                mma8(acc[1][j], ah[1], bh0, bh1);
            }
        }
        if (more) {
            CP_WAIT0;
            __syncthreads();
        }
    }

    // epilogue: scatter head-major. q: hi+lo. k/v: hi only.
#pragma unroll
    for (int i = 0; i < 2; i++) {
        const int mA = m0 + wm * 32 + i * 16 + g;
#pragma unroll
        for (int half = 0; half < 2; half++) {
            const int m = mA + half * 8;
            const int bb = m >> 10, n = m & 1023;
#pragma unroll
            for (int j = 0; j < 8; j++) {
                const int cg = n0 + wn * 64 + j * 8 + tg * 2;
                const float x0 = acc[i][j][half * 2];
                const float x1 = acc[i][j][half * 2 + 1];
                if (cg < 768) {
                    float2 vh, vl;
                    splitf(x0, vh.x, vl.x);
                    splitf(x1, vh.y, vl.y);
                    const int h = cg >> 6, d = cg & 63;
                    const size_t o = (((size_t)bb * NH + h) * NSEQ + n) * NDH + d;
                    *(float2*)&g_qh_hi[o] = vh;
                    *(float2*)&g_qh_lo[o] = vl;
                } else {
                    const int cc = cg - 768;
                    const bool isV = (cc >= 768);
                    const int c2 = isV ? cc - 768 : cc;
                    const int h = c2 >> 6, d = c2 & 63;
                    const size_t o = (((size_t)bb * NH + h) * NSEQ + n) * NDH + d;
                    float2 vh = make_float2(__uint_as_float(f2tf(x0)),
                                            __uint_as_float(f2tf(x1)));
                    *(float2*)&(isV ? g_vh_hi : g_kh_hi)[o] = vh;
                }
            }
        }
    }
}

// ---------------------------------------------------------------------------
// Kernel 2a: feature attention PARTIAL. grid (96, 4): block sums 256 n each.
// 2-mma (Q exact x K-hi). Raw partial S -> g_fpart.
// dsm: 2 bufs x (Qh 2304 | Ql 2304 | Kh 2304), stride 72. 13824 f = 55296 B.
// ---------------------------------------------------------------------------
__global__ __launch_bounds__(128) void fattn_partial() {
    extern __shared__ float dsm[];

    const int bh = blockIdx.x;
    const int nbase = blockIdx.y * 256;
    const size_t base = (size_t)bh * NSEQ * NDH;

    const int t = threadIdx.x, lane = t & 31, w = t >> 5;
    const int g = lane >> 2, tg = lane & 3;
    const int mb = w * 16 + g;

    auto stage = [&](int buf, int n0) {
        float* p = dsm + buf * 6912;
#pragma unroll
        for (int u = 0; u < 4; u++) {
            const int idx = t + u * 128;
            const int row = idx >> 4, colf = (idx & 15) * 4;
            const size_t go = base + (size_t)(nbase + n0 + row) * 64 + colf;
            cpa16(smem_u32(&p[row * 72 + colf]),        g_qh_hi + go);
            cpa16(smem_u32(&p[2304 + row * 72 + colf]), g_qh_lo + go);
            cpa16(smem_u32(&p[4608 + row * 72 + colf]), g_kh_hi + go);
        }
    };

    float acc[8][4] = {};
    stage(0, 0);
    CP_COMMIT;
    CP_WAIT0;
    __syncthreads();

    for (int n0 = 0; n0 < 256; n0 += 32) {
        const int cur = (n0 >> 5) & 1;
        float* Qh = dsm + cur * 6912;
        float* Ql = Qh + 2304;
        float* Kh = Qh + 4608;
        const bool more = (n0 + 32 < 256);
        if (more) {
            stage(cur ^ 1, n0 + 32);
            CP_COMMIT;
        }
#pragma unroll
        for (int kk = 0; kk < 4; kk++) {
            const int k = kk * 8;
            unsigned ah[4], al[4];
            ah[0] = u32(Qh[(k + tg) * 72 + mb]);
            ah[1] = u32(Qh[(k + tg) * 72 + mb + 8]);
            ah[2] = u32(Qh[(k + tg + 4) * 72 + mb]);
            ah[3] = u32(Qh[(k + tg + 4) * 72 + mb + 8]);
            al[0] = u32(Ql[(k + tg) * 72 + mb]);
            al[1] = u32(Ql[(k + tg) * 72 + mb + 8]);
            al[2] = u32(Ql[(k + tg + 4) * 72 + mb]);
            al[3] = u32(Ql[(k + tg + 4) * 72 + mb + 8]);
#pragma unroll
            for (int j = 0; j < 8; j++) {
                const int c = j * 8 + g;
                const unsigned bh0 = u32(Kh[(k + tg) * 72 + c]);
                const unsigned bh1 = u32(Kh[(k + tg + 4) * 72 + c]);
                mma8(acc[j], al, bh0, bh1);
                mma8(acc[j], ah, bh0, bh1);
            }
        }
        if (more) {
            CP_WAIT0;
            __syncthreads();
        }
    }

    float* outp = g_fpart + ((size_t)bh * 4 + blockIdx.y) * 4096;
#pragma unroll
    for (int j = 0; j < 8; j++) {
        const int r0 = w * 16 + g, c = j * 8 + tg * 2;
        *(float2*)&outp[r0 * 64 + c]       = make_float2(acc[j][0], acc[j][1]);
        *(float2*)&outp[(r0 + 8) * 64 + c] = make_float2(acc[j][2], acc[j][3]);
    }
}

// ---------------------------------------------------------------------------
// Kernel 2b: combine + softmax, smem-based (no register-array spill).
// grid 96, block 128. smem: Ss[64*65] + sinv[64].
// ---------------------------------------------------------------------------
__global__ __launch_bounds__(128) void fattn_combine() {
    __shared__ float Ss[64 * 65];
    __shared__ float sinv[64];
    const int bh = blockIdx.x, t = threadIdx.x;
    const float* p0 = g_fpart + ((size_t)bh * 4 + 0) * 4096;
    const float* p1 = g_fpart + ((size_t)bh * 4 + 1) * 4096;
    const float* p2 = g_fpart + ((size_t)bh * 4 + 2) * 4096;
    const float* p3 = g_fpart + ((size_t)bh * 4 + 3) * 4096;

    // cooperative sum: 4096 floats / 128 threads = 8 float4 each
#pragma unroll
    for (int u = 0; u < 8; u++) {
        const int f4 = t + u * 128;         // float4 index 0..1023
        float4 a = ((const float4*)p0)[f4];
        float4 b = ((const float4*)p1)[f4];
        float4 c = ((const float4*)p2)[f4];
        float4 d = ((const float4*)p3)[f4];
        const int e0 = f4 * 4;
        const int r = e0 >> 6, cc = e0 & 63;
        Ss[r * 65 + cc]     = ((a.x + b.x) + (c.x + d.x)) * SCALE;
        Ss[r * 65 + cc + 1] = ((a.y + b.y) + (c.y + d.y)) * SCALE;
        Ss[r * 65 + cc + 2] = ((a.z + b.z) + (c.z + d.z)) * SCALE;
        Ss[r * 65 + cc + 3] = ((a.w + b.w) + (c.w + d.w)) * SCALE;
    }
    __syncthreads();
    if (t < 64) {
        float mx = -INFINITY;
        for (int e = 0; e < 64; e++) mx = fmaxf(mx, Ss[t * 65 + e]);
        float s = 0.f;
        for (int e = 0; e < 64; e++) {
            float v = __expf(Ss[t * 65 + e] - mx);
            Ss[t * 65 + e] = v;
            s += v;
        }
        sinv[t] = 1.0f / s;
    }
    __syncthreads();
    float* outp = g_fattn + (size_t)bh * 4096;
    for (int idx = t; idx < 4096; idx += 128) {
        const int r = idx >> 6;
        outp[idx] = __uint_as_float(f2tf(Ss[r * 65 + (idx & 63)] * sinv[r]));
    }
}

// ---------------------------------------------------------------------------
// Kernel 3: flash attention + feature apply. FIXED-MAX softmax, 3 CTAs/SM. (R11)
// ---------------------------------------------------------------------------
__global__ __launch_bounds__(128, 3) void attn_kernel() {
    extern __shared__ float dsm[];

    const int bh = blockIdx.y;
    const int n0q = blockIdx.x * 64;
    const size_t base = (size_t)bh * NSEQ * NDH;

    const int t = threadIdx.x, lane = t & 31, w = t >> 5;
    const int g = lane >> 2, tg = lane & 3;

    auto stageKV = [&](int buf, int c0) {
        float* Kh = dsm + 8704 + buf * 2176;
        float* Vh = dsm + 13056 + buf * 2304;
#pragma unroll
        for (int u = 0; u < 4; u++) {
            const int idx = t + u * 128;
            const int row = idx >> 4, colf = (idx & 15) * 4;
            const size_t go = base + (size_t)(c0 + row) * 64 + colf;
            cpa16(smem_u32(&Kh[row * 68 + colf]), g_kh_hi + go);
            cpa16(smem_u32(&Vh[row * 72 + colf]), g_vh_hi + go);
        }
    };

#pragma unroll
    for (int u = 0; u < 8; u++) {
        const int idx = t + u * 128;
        const int row = idx >> 4, colf = (idx & 15) * 4;
        const size_t go = base + (size_t)(n0q + row) * 64 + colf;
        cpa16(smem_u32(&dsm[row * 68 + colf]),        g_qh_hi + go);
        cpa16(smem_u32(&dsm[4352 + row * 68 + colf]), g_qh_lo + go);
    }
    stageKV(0, 0);
    CP_COMMIT;
    CP_WAIT0;
    __syncthreads();

    unsigned qfh[8][4], qfl[8][4];
    {
        const int rb = w * 16 + g;
#pragma unroll
        for (int kk = 0; kk < 8; kk++) {
            const int k = kk * 8;
            qfh[kk][0] = u32(dsm[rb * 68 + k + tg]);
            qfh[kk][1] = u32(dsm[(rb + 8) * 68 + k + tg]);
            qfh[kk][2] = u32(dsm[rb * 68 + k + tg + 4]);
            qfh[kk][3] = u32(dsm[(rb + 8) * 68 + k + tg + 4]);
            qfl[kk][0] = u32(dsm[4352 + rb * 68 + k + tg]);
            qfl[kk][1] = u32(dsm[4352 + (rb + 8) * 68 + k + tg]);
            qfl[kk][2] = u32(dsm[4352 + rb * 68 + k + tg + 4]);
            qfl[kk][3] = u32(dsm[4352 + (rb + 8) * 68 + k + tg + 4]);
        }
    }
    __syncthreads();   // Q region now reusable (P)

    float O[8][4] = {};
    float l0 = 0.f, l1 = 0.f;
    float* Pw = dsm + w * 576;

    for (int c0 = 0; c0 < NSEQ; c0 += 32) {
        const int cur = (c0 >> 5) & 1;
        float* Kh = dsm + 8704 + cur * 2176;
        float* Vh = dsm + 13056 + cur * 2304;
        const bool more = (c0 + 32 < NSEQ);
        if (more) {
            stageKV(cur ^ 1, c0 + 32);
            CP_COMMIT;
        }

        float sacc[4][4] = {};
#pragma unroll
        for (int kk = 0; kk < 8; kk++) {
            const int k = kk * 8;
#pragma unroll
            for (int j = 0; j < 4; j++) {
                const int c = j * 8 + g;
                const unsigned bh0 = u32(Kh[c * 68 + k + tg]);
                const unsigned bh1 = u32(Kh[c * 68 + k + tg + 4]);
                mma8(sacc[j], qfl[kk], bh0, bh1);
                mma8(sacc[j], qfh[kk], bh0, bh1);
            }
        }

#pragma unroll
        for (int j = 0; j < 4; j++) {
            const float p00 = __expf(fmaf(sacc[j][0], SCALE, -FIXMAX));
            const float p01 = __expf(fmaf(sacc[j][1], SCALE, -FIXMAX));
            const float p10 = __expf(fmaf(sacc[j][2], SCALE, -FIXMAX));
            const float p11 = __expf(fmaf(sacc[j][3], SCALE, -FIXMAX));
            l0 += p00 + p01;
            l1 += p10 + p11;
            const int c = j * 8 + tg * 2;
            Pw[g * 36 + c]           = __uint_as_float(f2tf(p00));
            Pw[g * 36 + c + 1]       = __uint_as_float(f2tf(p01));
            Pw[(g + 8) * 36 + c]     = __uint_as_float(f2tf(p10));
            Pw[(g + 8) * 36 + c + 1] = __uint_as_float(f2tf(p11));
        }
        __syncwarp();

#pragma unroll
        for (int kk = 0; kk < 4; kk++) {
            const int k = kk * 8;
            unsigned a[4];
            a[0] = u32(Pw[g * 36 + k + tg]);
            a[1] = u32(Pw[(g + 8) * 36 + k + tg]);
            a[2] = u32(Pw[g * 36 + k + tg + 4]);
            a[3] = u32(Pw[(g + 8) * 36 + k + tg + 4]);
#pragma unroll
            for (int nt = 0; nt < 8; nt++) {
                const unsigned b0 = u32(Vh[(k + tg) * 72 + nt * 8 + g]);
                const unsigned b1 = u32(Vh[(k + tg + 4) * 72 + nt * 8 + g]);
                mma8(O[nt], a, b0, b1);
            }
        }

        if (more) {
            CP_WAIT0;
        }
        __syncthreads();
    }

    l0 += __shfl_xor_sync(0xffffffffu, l0, 1);
    l0 += __shfl_xor_sync(0xffffffffu, l0, 2);
    l1 += __shfl_xor_sync(0xffffffffu, l1, 1);
    l1 += __shfl_xor_sync(0xffffffffu, l1, 2);
    const float i0 = 1.0f / l0, i1 = 1.0f / l1;
#pragma unroll
    for (int nt = 0; nt < 8; nt++) {
        O[nt][0] *= i0; O[nt][1] *= i0;
        O[nt][2] *= i1; O[nt][3] *= i1;
    }

    // feature path
    float* Fa  = dsm;
    float* Vqh = dsm + 4352;
    const float* Fg = g_fattn + (size_t)bh * 4096;
    {
#pragma unroll
        for (int u = 0; u < 8; u++) {
            const int idx = t + u * 128;
            const int row = idx >> 4, colf = (idx & 15) * 4;
            const size_t go = base + (size_t)(n0q + row) * 64 + colf;
            cpa16(smem_u32(&Fa[row * 68 + colf]), Fg + (size_t)row * 64 + colf);
            cpa16(smem_u32(&Vqh[row * 68 + colf]), g_vh_hi + go);
        }
    }
    CP_COMMIT;
    CP_WAIT0;
    __syncthreads();
    {
        const int rb = w * 16 + g;
#pragma unroll
        for (int kk = 0; kk < 8; kk++) {
            const int k = kk * 8;
            unsigned a[4];
            a[0] = u32(Vqh[rb * 68 + k + tg]);
            a[1] = u32(Vqh[(rb + 8) * 68 + k + tg]);
            a[2] = u32(Vqh[rb * 68 + k + tg + 4]);
            a[3] = u32(Vqh[(rb + 8) * 68 + k + tg + 4]);
#pragma unroll
            for (int nt = 0; nt < 8; nt++) {
                const unsigned b0 = u32(Fa[(nt * 8 + g) * 68 + k + tg]);
                const unsigned b1 = u32(Fa[(nt * 8 + g) * 68 + k + tg + 4]);
                mma8(O[nt], a, b0, b1);
            }
        }
    }

    const int bb = bh / NH, h = bh - bb * NH;
    const int r0 = n0q + w * 16 + g;
#pragma unroll
    for (int nt = 0; nt < 8; nt++) {
        const int col = h * 64 + nt * 8 + tg * 2;
        *(float2*)&g_tmp[((size_t)bb * NSEQ + r0) * NC + col] =
            make_float2(O[nt][0], O[nt][1]);
        *(float2*)&g_tmp[((size_t)bb * NSEQ + r0 + 8) * NC + col] =
            make_float2(O[nt][2], O[nt][3]);
    }
}

// ---------------------------------------------------------------------------
// Kernel 4: output projection, 3xtf32 (guards the error budget). (R11)
// ---------------------------------------------------------------------------
__global__ __launch_bounds__(256, 2) void proj_gemm(const float* __restrict__ bias,
                                                    float* __restrict__ out) {
    extern __shared__ float dsm[];

    const int n0 = blockIdx.x * 128;
    const int m0 = blockIdx.y * 128;
    const int t = threadIdx.x, lane = t & 31, w = t >> 5;
    const int g = lane >> 2, tg = lane & 3;
    const int wm = w & 3, wn = w >> 2;

    auto stageA = [&](float* As, int k0) {
#pragma unroll
        for (int u = 0; u < 4; u++) {
            const int idx = t + u * 256;
            const int row = idx >> 3, colf = (idx & 7) * 4;
            cpa16(smem_u32(&As[row * 36 + colf]),
                  g_tmp + (size_t)(m0 + row) * 768 + k0 + colf);
        }
    };
    auto stageB = [&](float* Bh, float* Bl, int k0) {
#pragma unroll
        for (int u = 0; u < 4; u++) {
            const int idx = t + u * 256;
            const int row = idx >> 5, col = (idx & 31) * 4;
            const size_t go = (size_t)(k0 + row) * 768 + n0 + col;
            cpa16(smem_u32(&Bh[row * 136 + col]), g_Wp_hi + go);
            cpa16(smem_u32(&Bl[row * 136 + col]), g_Wp_lo + go);
        }
    };

    float acc[2][8][4] = {};

    stageA(dsm, 0);
    stageB(dsm + 9216, dsm + 9216 + 4352, 0);
    CP_COMMIT;
    CP_WAIT0;
    __syncthreads();

    for (int k0 = 0; k0 < 768; k0 += 32) {
        const int cur = (k0 >> 5) & 1;
        float* As = dsm + cur * 4608;
        float* Bh = dsm + 9216 + cur * 8704;
        float* Bl = Bh + 4352;
        const bool more = (k0 + 32 < 768);
        if (more) {
            stageA(dsm + (cur ^ 1) * 4608, k0 + 32);
            stageB(dsm + 9216 + (cur ^ 1) * 8704,
                   dsm + 9216 + (cur ^ 1) * 8704 + 4352, k0 + 32);
            CP_COMMIT;
        }
#pragma unroll
        for (int kk = 0; kk < 4; kk++) {
            const int k = kk * 8;
            unsigned ah[2][4], al[2][4];
#pragma unroll
            for (int i = 0; i < 2; i++) {
                const int rb = wm * 32 + i * 16 + g;
                split(As[rb * 36 + k + tg],           ah[i][0], al[i][0]);
                split(As[(rb + 8) * 36 + k + tg],     ah[i][1], al[i][1]);
                split(As[rb * 36 + k + tg + 4],       ah[i][2], al[i][2]);
                split(As[(rb + 8) * 36 + k + tg + 4], ah[i][3], al[i][3]);
            }
#pragma unroll
            for (int j = 0; j < 8; j++) {
                const int c = wn * 64 + j * 8 + g;
                const unsigned bh0 = u32(Bh[(k + tg) * 136 + c]);
                const unsigned bh1 = u32(Bh[(k + tg + 4) * 136 + c]);
                const unsigned bl0 = u32(Bl[(k + tg) * 136 + c]);
                const unsigned bl1 = u32(Bl[(k + tg + 4) * 136 + c]);
                mma3(acc[0][j], ah[0], al[0], bh0, bh1, bl0, bl1);
                mma3(acc[1][j], ah[1], al[1], bh0, bh1, bl0, bl1);
            }
        }
        if (more) {
            CP_WAIT0;
            __syncthreads();
        }
    }

#pragma unroll
    for (int i = 0; i < 2; i++) {
        const int mA = m0 + wm * 32 + i * 16 + g;
#pragma unroll
        for (int half = 0; half < 2; half++) {
            const size_t m = mA + half * 8;
#pragma unroll
            for (int j = 0; j < 8; j++) {
                const int c = n0 + wn * 64 + j * 8 + tg * 2;
                float2 v = make_float2(acc[i][j][half * 2] + bias[c],
                                       acc[i][j][half * 2 + 1] + bias[c + 1]);
                *(float2*)&out[m * 768 + c] = v;
            }
        }
    }
}

// ---------------------------------------------------------------------------
extern "C" void kernel_launch(void* const* d_in, const int* in_sizes, int n_in,
                              void* d_out, int out_size) {
    const float* q     = (const float*)d_in[0];
    const float* k     = (const float*)d_in[1];
    const float* Wq    = (const float*)d_in[2];
    const float* Wkv   = (const float*)d_in[3];
    const float* Wproj = (const float*)d_in[4];
    const float* bproj = (const float*)d_in[5];
    float* out = (float*)d_out;

    const int smemQ = 17920 * 4;   // 71680 B
    const int smemP = 26624 * 4;   // 106496 B
    const int smemA = 17664 * 4;   // 70656 B
    const int smemF = 13824 * 4;   // 55296 B
    cudaFuncSetAttribute(qkv_gemm, cudaFuncAttributeMaxDynamicSharedMemorySize, smemQ);
    cudaFuncSetAttribute(proj_gemm, cudaFuncAttributeMaxDynamicSharedMemorySize, smemP);
    cudaFuncSetAttribute(attn_kernel, cudaFuncAttributeMaxDynamicSharedMemorySize, smemA);
    cudaFuncSetAttribute(fattn_partial, cudaFuncAttributeMaxDynamicSharedMemorySize, smemF);

    prep_split<<<2304, 256>>>(Wq, Wkv, Wproj);
    qkv_gemm<<<dim3(18, 64), 256, smemQ>>>(q, k);
    fattn_partial<<<dim3(96, 4), 128, smemF>>>();
    fattn_combine<<<96, 128>>>();
    attn_kernel<<<dim3(16, 96), 128, smemA>>>();
    proj_gemm<<<dim3(6, 64), 256, smemP>>>(bproj, out);
}